// round 1
// baseline (speedup 1.0000x reference)
#include <cuda_runtime.h>

#define BDIM 256
#define WPB 8          // warps (MLPs) per block
#define PSTRIDE 272    // per-MLP smem floats (16B-aligned stride)

__constant__ float c_lr[6] = {0.001f, 0.01f, 0.05f, 0.1f, 0.5f, 1.0f};
__device__ float g_sumsq;

__device__ __forceinline__ float clip1e4(float v) {
    return fminf(fmaxf(v, -10000.f), 10000.f);
}

__global__ void k_zero() { g_sumsq = 0.f; }

// Butterfly-reduce v over the warp; owning lane writes and accumulates sumsq.
#define RED(v, idx) do {                                        \
    float _v = (v);                                             \
    _v += __shfl_xor_sync(0xffffffffu, _v, 16);                 \
    _v += __shfl_xor_sync(0xffffffffu, _v, 8);                  \
    _v += __shfl_xor_sync(0xffffffffu, _v, 4);                  \
    _v += __shfl_xor_sync(0xffffffffu, _v, 2);                  \
    _v += __shfl_xor_sync(0xffffffffu, _v, 1);                  \
    if (lane == ((idx) & 31)) {                                 \
        gout[(idx)] = _v;                                       \
        ssq = fmaf(_v, _v, ssq);                                \
    }                                                           \
} while (0)

__global__ void __launch_bounds__(BDIM, 1) k_main(
    const float* __restrict__ W1, const float* __restrict__ b1,
    const float* __restrict__ W2, const float* __restrict__ b2,
    const float* __restrict__ W3, const float* __restrict__ b3,
    const float* __restrict__ G1, const float* __restrict__ G2,
    const float* __restrict__ G3, const float* __restrict__ G4,
    const float* __restrict__ G5, const float* __restrict__ G6,
    const float* __restrict__ dx, const float* __restrict__ fv,
    const int* __restrict__ dy, const int* __restrict__ ss,
    float* __restrict__ out)
{
    __shared__ __align__(16) float xs[600];   // data_x [150,4]
    __shared__ int ys[152];                   // data_y
    __shared__ __align__(16) float ps[WPB * PSTRIDE];

    const int tid  = threadIdx.x;
    const int lane = tid & 31;
    const int warp = tid >> 5;
    const int b    = blockIdx.x * WPB + warp;

    for (int i = tid; i < 600; i += BDIM) xs[i] = dx[i];
    for (int i = tid; i < 150; i += BDIM) ys[i] = dy[i];

    float* P = ps + warp * PSTRIDE;
    // SMEM layout (floats):
    //   0: W1 [10x4]   40: b1[10]   52: W2 rows stride 12 (10 rows)
    // 172: b2[10]     184: W3 rows stride 12 (3 rows)   220: b3[3]
    // 224: W3^T rows stride 4 (10 rows, [g][o])

    const float lr = c_lr[ss[b]];
    float* wout = out + (size_t)b * 388;

    // ---- SGD update into SMEM, clipped params to output ----
    for (int k = lane; k < 40; k += 32) {
        float p = fmaf(-lr, G1[b * 40 + k], W1[b * 40 + k]);
        P[k] = p; wout[k] = clip1e4(p);
    }
    for (int k = lane; k < 10; k += 32) {
        float p = fmaf(-lr, G2[b * 10 + k], b1[b * 10 + k]);
        P[40 + k] = p; wout[40 + k] = clip1e4(p);
    }
    for (int k = lane; k < 100; k += 32) {
        float p = fmaf(-lr, G3[b * 100 + k], W2[b * 100 + k]);
        int r = k / 10, c = k - r * 10;
        P[52 + 12 * r + c] = p; wout[50 + k] = clip1e4(p);
    }
    for (int k = lane; k < 10; k += 32) {
        float p = fmaf(-lr, G4[b * 10 + k], b2[b * 10 + k]);
        P[172 + k] = p; wout[150 + k] = clip1e4(p);
    }
    for (int k = lane; k < 30; k += 32) {
        float p = fmaf(-lr, G5[b * 30 + k], W3[b * 30 + k]);
        int r = k / 10, c = k - r * 10;
        P[184 + 12 * r + c] = p;
        P[224 + 4 * c + r]  = p;   // transpose for dh2
        wout[160 + k] = clip1e4(p);
    }
    for (int k = lane; k < 3; k += 32) {
        float p = fmaf(-lr, G6[b * 3 + k], b3[b * 3 + k]);
        P[220 + k] = p; wout[190 + k] = clip1e4(p);
    }
    __syncthreads();

    // ---- grad accumulators (registers) ----
    float gW1[40] = {}, gB1[10] = {}, gW2[100] = {}, gB2[10] = {},
          gW3[30] = {}, gB3[3] = {};
    float lossacc = 0.f;

    for (int s = lane; s < 150; s += 32) {
        const float4 xv = *(const float4*)&xs[4 * s];
        const int y = ys[s];

        // layer 1
        float h1[10];
#pragma unroll
        for (int j = 0; j < 10; j++) {
            float4 w = *(const float4*)&P[4 * j];
            float a = fmaf(w.x, xv.x, w.y * xv.y);
            float c = fmaf(w.z, xv.z, w.w * xv.w);
            h1[j] = fmaxf(a + c + P[40 + j], 0.f);
        }
        // layer 2
        float h2[10];
#pragma unroll
        for (int g = 0; g < 10; g++) {
            const float* r = &P[52 + 12 * g];
            float4 wa = *(const float4*)r;
            float4 wb = *(const float4*)(r + 4);
            float a = fmaf(wa.x, h1[0], fmaf(wa.z, h1[2],
                      fmaf(wb.x, h1[4], fmaf(wb.z, h1[6], r[8] * h1[8]))));
            float c = fmaf(wa.y, h1[1], fmaf(wa.w, h1[3],
                      fmaf(wb.y, h1[5], fmaf(wb.w, h1[7], r[9] * h1[9]))));
            h2[g] = fmaxf(a + c + P[172 + g], 0.f);
        }
        // layer 3 logits
        float lg[3];
#pragma unroll
        for (int o = 0; o < 3; o++) {
            const float* r = &P[184 + 12 * o];
            float4 wa = *(const float4*)r;
            float4 wb = *(const float4*)(r + 4);
            float a = fmaf(wa.x, h2[0], fmaf(wa.z, h2[2],
                      fmaf(wb.x, h2[4], fmaf(wb.z, h2[6], r[8] * h2[8]))));
            float c = fmaf(wa.y, h2[1], fmaf(wa.w, h2[3],
                      fmaf(wb.y, h2[5], fmaf(wb.w, h2[7], r[9] * h2[9]))));
            lg[o] = a + c + P[220 + o];
        }

        // softmax + CE loss
        float m  = fmaxf(lg[0], fmaxf(lg[1], lg[2]));
        float e0 = __expf(lg[0] - m), e1 = __expf(lg[1] - m), e2 = __expf(lg[2] - m);
        float sum = e0 + e1 + e2;
        float inv = __fdividef(1.f, sum);
        float ly  = (y == 0) ? lg[0] : ((y == 1) ? lg[1] : lg[2]);
        lossacc += (m - ly) + __logf(sum);

        const float invN = 1.f / 150.f;
        float d0 = (e0 * inv - (y == 0 ? 1.f : 0.f)) * invN;
        float d1 = (e1 * inv - (y == 1 ? 1.f : 0.f)) * invN;
        float d2 = (e2 * inv - (y == 2 ? 1.f : 0.f)) * invN;

        // dW3 / db3
        gB3[0] += d0; gB3[1] += d1; gB3[2] += d2;
#pragma unroll
        for (int g = 0; g < 10; g++) {
            gW3[g]      = fmaf(d0, h2[g], gW3[g]);
            gW3[10 + g] = fmaf(d1, h2[g], gW3[10 + g]);
            gW3[20 + g] = fmaf(d2, h2[g], gW3[20 + g]);
        }

        // per-g: dh2_g scalar, fuse dW2 row / db2 / dh1 accumulation
        float dh1[10];
#pragma unroll
        for (int h = 0; h < 10; h++) dh1[h] = 0.f;
#pragma unroll
        for (int g = 0; g < 10; g++) {
            float4 wt = *(const float4*)&P[224 + 4 * g];   // W3^T row g
            float dg = fmaf(wt.x, d0, fmaf(wt.y, d1, wt.z * d2));
            dg = (h2[g] > 0.f) ? dg : 0.f;
            gB2[g] += dg;
            const float* r = &P[52 + 12 * g];
            float4 wa = *(const float4*)r;
            float4 wb = *(const float4*)(r + 4);
            float w[10] = {wa.x, wa.y, wa.z, wa.w, wb.x, wb.y, wb.z, wb.w,
                           r[8], r[9]};
#pragma unroll
            for (int h = 0; h < 10; h++) {
                gW2[g * 10 + h] = fmaf(dg, h1[h], gW2[g * 10 + h]);
                dh1[h] = fmaf(dg, w[h], dh1[h]);
            }
        }
        // layer-1 grads
#pragma unroll
        for (int h = 0; h < 10; h++) {
            float dh = (h1[h] > 0.f) ? dh1[h] : 0.f;
            gB1[h] += dh;
            gW1[4 * h + 0] = fmaf(dh, xv.x, gW1[4 * h + 0]);
            gW1[4 * h + 1] = fmaf(dh, xv.y, gW1[4 * h + 1]);
            gW1[4 * h + 2] = fmaf(dh, xv.z, gW1[4 * h + 2]);
            gW1[4 * h + 3] = fmaf(dh, xv.w, gW1[4 * h + 3]);
        }
    }

    // ---- loss reduction ----
    lossacc += __shfl_xor_sync(0xffffffffu, lossacc, 16);
    lossacc += __shfl_xor_sync(0xffffffffu, lossacc, 8);
    lossacc += __shfl_xor_sync(0xffffffffu, lossacc, 4);
    lossacc += __shfl_xor_sync(0xffffffffu, lossacc, 2);
    lossacc += __shfl_xor_sync(0xffffffffu, lossacc, 1);
    const float loss_b = lossacc * (1.f / 150.f);

    // ---- grad reduction across lanes, raw grads to output, sumsq ----
    float ssq = 0.f;
    float* gout = wout + 193;
#pragma unroll
    for (int k = 0; k < 40; k++)  RED(gW1[k], k);
#pragma unroll
    for (int k = 0; k < 10; k++)  RED(gB1[k], 40 + k);
#pragma unroll
    for (int k = 0; k < 100; k++) RED(gW2[k], 50 + k);
#pragma unroll
    for (int k = 0; k < 10; k++)  RED(gB2[k], 150 + k);
#pragma unroll
    for (int k = 0; k < 30; k++)  RED(gW3[k], 160 + k);
#pragma unroll
    for (int k = 0; k < 3; k++)   RED(gB3[k], 190 + k);

    ssq += __shfl_xor_sync(0xffffffffu, ssq, 16);
    ssq += __shfl_xor_sync(0xffffffffu, ssq, 8);
    ssq += __shfl_xor_sync(0xffffffffu, ssq, 4);
    ssq += __shfl_xor_sync(0xffffffffu, ssq, 2);
    ssq += __shfl_xor_sync(0xffffffffu, ssq, 1);

    if (lane == 0) {
        atomicAdd(&g_sumsq, ssq);
        wout[386] = loss_b;
        wout[387] = clip1e4(fv[b] - loss_b);
    }
}

// Apply global grad-norm clip coefficient to the grad columns [193, 386).
__global__ void k_scale(float* __restrict__ out) {
    const float coef = fminf(1.f, 10.f / (sqrtf(g_sumsq) + 1e-6f));
    const int b = blockIdx.x;
    const int k = threadIdx.x;
    if (k < 193) {
        size_t idx = (size_t)b * 388 + 193 + k;
        out[idx] *= coef;
    }
}

extern "C" void kernel_launch(void* const* d_in, const int* in_sizes, int n_in,
                              void* d_out, int out_size)
{
    const float* W1 = (const float*)d_in[0];
    const float* b1 = (const float*)d_in[1];
    const float* W2 = (const float*)d_in[2];
    const float* b2 = (const float*)d_in[3];
    const float* W3 = (const float*)d_in[4];
    const float* b3 = (const float*)d_in[5];
    const float* G1 = (const float*)d_in[6];
    const float* G2 = (const float*)d_in[7];
    const float* G3 = (const float*)d_in[8];
    const float* G4 = (const float*)d_in[9];
    const float* G5 = (const float*)d_in[10];
    const float* G6 = (const float*)d_in[11];
    const float* dx = (const float*)d_in[12];
    const float* fv = (const float*)d_in[13];
    const int*   dy = (const int*)d_in[14];
    const int*   ss = (const int*)d_in[15];
    float* out = (float*)d_out;

    const int B = in_sizes[13];   // func_val is [B]

    k_zero<<<1, 1>>>();
    k_main<<<B / WPB, BDIM>>>(W1, b1, W2, b2, W3, b3,
                              G1, G2, G3, G4, G5, G6,
                              dx, fv, dy, ss, out);
    k_scale<<<B, 256>>>(out);
}

// round 2
// speedup vs baseline: 1.6160x; 1.6160x over previous
#include <cuda_runtime.h>

#define BDIM 64
#define WPB 2            // warps (MLPs) per block
#define RS 153           // rec row stride in floats (odd -> conflict-free)
#define RECW (23 * RS)   // per-warp rec floats: rows dh1m[10], h2[10], d[3]
#define PSTRIDE 272      // per-MLP param smem floats

__constant__ float c_lr[6] = {0.001f, 0.01f, 0.05f, 0.1f, 0.5f, 1.0f};
__device__ float g_sumsq;

__device__ __forceinline__ float clip1e4(float v) {
    return fminf(fmaxf(v, -10000.f), 10000.f);
}

__global__ void k_zero() { g_sumsq = 0.f; }

__global__ void __launch_bounds__(BDIM) k_main(
    const float* __restrict__ W1, const float* __restrict__ b1,
    const float* __restrict__ W2, const float* __restrict__ b2,
    const float* __restrict__ W3, const float* __restrict__ b3,
    const float* __restrict__ G1, const float* __restrict__ G2,
    const float* __restrict__ G3, const float* __restrict__ G4,
    const float* __restrict__ G5, const float* __restrict__ G6,
    const float* __restrict__ dx, const float* __restrict__ fv,
    const int* __restrict__ dy, const int* __restrict__ ss,
    float* __restrict__ out)
{
    // xsT rows 0..3 = x features (transposed), row 4 = ones
    __shared__ float xsT[5 * RS];
    __shared__ int   ys[152];
    __shared__ __align__(16) float ps[WPB * PSTRIDE];
    __shared__ float rec[WPB * RECW];

    const int tid  = threadIdx.x;
    const int lane = tid & 31;
    const int warp = tid >> 5;
    const int b    = blockIdx.x * WPB + warp;

    for (int i = tid; i < 150; i += BDIM) {
        const float4 xv = ((const float4*)dx)[i];
        xsT[0 * RS + i] = xv.x;
        xsT[1 * RS + i] = xv.y;
        xsT[2 * RS + i] = xv.z;
        xsT[3 * RS + i] = xv.w;
        xsT[4 * RS + i] = 1.f;
        ys[i] = dy[i];
    }

    float* P    = ps  + warp * PSTRIDE;
    float* recW = rec + warp * RECW;
    // P layout (floats): 0:W1[10x4]  40:b1[10]  52:W2 rows stride 12 (10 rows)
    // 172:b2[10]  184:W3 rows stride 12 (3 rows)  220:b3[3]  224:W3^T stride 4

    const float lr = c_lr[ss[b]];
    float* wout = out + (size_t)b * 388;

    // ---- SGD update into SMEM, clipped params to output ----
    for (int k = lane; k < 40; k += 32) {
        float p = fmaf(-lr, G1[b * 40 + k], W1[b * 40 + k]);
        P[k] = p; wout[k] = clip1e4(p);
    }
    for (int k = lane; k < 10; k += 32) {
        float p = fmaf(-lr, G2[b * 10 + k], b1[b * 10 + k]);
        P[40 + k] = p; wout[40 + k] = clip1e4(p);
    }
    for (int k = lane; k < 100; k += 32) {
        float p = fmaf(-lr, G3[b * 100 + k], W2[b * 100 + k]);
        int r = k / 10, c = k - r * 10;
        P[52 + 12 * r + c] = p; wout[50 + k] = clip1e4(p);
    }
    for (int k = lane; k < 12; k += 32) {            // pad W2 rows' tail
        if (k >= 10) { P[52 + 12 * 9 + k] = 0.f; }
    }
    for (int k = lane; k < 10; k += 32) {
        float p = fmaf(-lr, G4[b * 10 + k], b2[b * 10 + k]);
        P[172 + k] = p; wout[150 + k] = clip1e4(p);
    }
    for (int k = lane; k < 30; k += 32) {
        float p = fmaf(-lr, G5[b * 30 + k], W3[b * 30 + k]);
        int r = k / 10, c = k - r * 10;
        P[184 + 12 * r + c] = p;
        P[224 + 4 * c + r]  = p;                     // W3^T for dh2
        wout[160 + k] = clip1e4(p);
    }
    for (int k = lane; k < 3; k += 32) {
        float p = fmaf(-lr, G6[b * 3 + k], b3[b * 3 + k]);
        P[220 + k] = p; wout[190 + k] = clip1e4(p);
    }
    __syncthreads();

    // ---- in-register accumulators: gW2 (0..99), gB2 (100..109), pad to 128
    float accR[128];
#pragma unroll
    for (int k = 0; k < 128; k++) accR[k] = 0.f;
    float lossacc = 0.f;
    const float invN = 1.f / 150.f;

    for (int s = lane; s < 150; s += 32) {
        const float xv0 = xsT[0 * RS + s], xv1 = xsT[1 * RS + s];
        const float xv2 = xsT[2 * RS + s], xv3 = xsT[3 * RS + s];
        const int y = ys[s];

        // layer 1
        float h1[10];
#pragma unroll
        for (int j = 0; j < 10; j++) {
            float4 w = *(const float4*)&P[4 * j];
            float a = fmaf(w.x, xv0, w.y * xv1);
            float c = fmaf(w.z, xv2, w.w * xv3);
            h1[j] = fmaxf(a + c + P[40 + j], 0.f);
        }
        // layer 2
        float h2[10];
#pragma unroll
        for (int g = 0; g < 10; g++) {
            const float* r = &P[52 + 12 * g];
            float4 wa = *(const float4*)r;
            float4 wb = *(const float4*)(r + 4);
            float a = fmaf(wa.x, h1[0], fmaf(wa.z, h1[2],
                      fmaf(wb.x, h1[4], fmaf(wb.z, h1[6], r[8] * h1[8]))));
            float c = fmaf(wa.y, h1[1], fmaf(wa.w, h1[3],
                      fmaf(wb.y, h1[5], fmaf(wb.w, h1[7], r[9] * h1[9]))));
            float v = fmaxf(a + c + P[172 + g], 0.f);
            h2[g] = v;
            recW[(10 + g) * RS + s] = v;             // store h2 row
        }
        // layer 3 logits
        float lg[3];
#pragma unroll
        for (int o = 0; o < 3; o++) {
            const float* r = &P[184 + 12 * o];
            float4 wa = *(const float4*)r;
            float4 wb = *(const float4*)(r + 4);
            float a = fmaf(wa.x, h2[0], fmaf(wa.z, h2[2],
                      fmaf(wb.x, h2[4], fmaf(wb.z, h2[6], r[8] * h2[8]))));
            float c = fmaf(wa.y, h2[1], fmaf(wa.w, h2[3],
                      fmaf(wb.y, h2[5], fmaf(wb.w, h2[7], r[9] * h2[9]))));
            lg[o] = a + c + P[220 + o];
        }

        // softmax + CE loss
        float m  = fmaxf(lg[0], fmaxf(lg[1], lg[2]));
        float e0 = __expf(lg[0] - m), e1 = __expf(lg[1] - m), e2 = __expf(lg[2] - m);
        float sum = e0 + e1 + e2;
        float inv = __fdividef(1.f, sum);
        float ly  = (y == 0) ? lg[0] : ((y == 1) ? lg[1] : lg[2]);
        lossacc += (m - ly) + __logf(sum);

        float d0 = (e0 * inv - (y == 0 ? 1.f : 0.f)) * invN;
        float d1 = (e1 * inv - (y == 1 ? 1.f : 0.f)) * invN;
        float d2 = (e2 * inv - (y == 2 ? 1.f : 0.f)) * invN;
        recW[20 * RS + s] = d0;                      // store d rows
        recW[21 * RS + s] = d1;
        recW[22 * RS + s] = d2;

        // per-g: dh2m scalar -> gB2, gW2, dh1
        float dh1[10];
#pragma unroll
        for (int h = 0; h < 10; h++) dh1[h] = 0.f;
#pragma unroll
        for (int g = 0; g < 10; g++) {
            float4 wt = *(const float4*)&P[224 + 4 * g];   // W3^T row g
            float dg = fmaf(wt.x, d0, fmaf(wt.y, d1, wt.z * d2));
            dg = (h2[g] > 0.f) ? dg : 0.f;
            accR[100 + g] += dg;                           // gB2
            const float* r = &P[52 + 12 * g];
            float4 wa = *(const float4*)r;
            float4 wb = *(const float4*)(r + 4);
            float4 wc = *(const float4*)(r + 8);           // .x,.y valid
            accR[g * 10 + 0] = fmaf(dg, h1[0], accR[g * 10 + 0]);
            accR[g * 10 + 1] = fmaf(dg, h1[1], accR[g * 10 + 1]);
            accR[g * 10 + 2] = fmaf(dg, h1[2], accR[g * 10 + 2]);
            accR[g * 10 + 3] = fmaf(dg, h1[3], accR[g * 10 + 3]);
            accR[g * 10 + 4] = fmaf(dg, h1[4], accR[g * 10 + 4]);
            accR[g * 10 + 5] = fmaf(dg, h1[5], accR[g * 10 + 5]);
            accR[g * 10 + 6] = fmaf(dg, h1[6], accR[g * 10 + 6]);
            accR[g * 10 + 7] = fmaf(dg, h1[7], accR[g * 10 + 7]);
            accR[g * 10 + 8] = fmaf(dg, h1[8], accR[g * 10 + 8]);
            accR[g * 10 + 9] = fmaf(dg, h1[9], accR[g * 10 + 9]);
            dh1[0] = fmaf(dg, wa.x, dh1[0]);
            dh1[1] = fmaf(dg, wa.y, dh1[1]);
            dh1[2] = fmaf(dg, wa.z, dh1[2]);
            dh1[3] = fmaf(dg, wa.w, dh1[3]);
            dh1[4] = fmaf(dg, wb.x, dh1[4]);
            dh1[5] = fmaf(dg, wb.y, dh1[5]);
            dh1[6] = fmaf(dg, wb.z, dh1[6]);
            dh1[7] = fmaf(dg, wb.w, dh1[7]);
            dh1[8] = fmaf(dg, wc.x, dh1[8]);
            dh1[9] = fmaf(dg, wc.y, dh1[9]);
        }
        // masked layer-1 deltas -> rec rows (gW1/gB1 offloaded)
#pragma unroll
        for (int h = 0; h < 10; h++) {
            recW[h * RS + s] = (h1[h] > 0.f) ? dh1[h] : 0.f;
        }
    }
    __syncwarp();

    float ssq = 0.f;
    float* gout = wout + 193;

    // ---- mini-pass: 83 offloaded params as length-150 dot products ----
    // slots: 0..39 gW1[h= s/4][f= s%4], 40..49 gB1, 50..79 gW3[o][g], 80..82 gB3
    const float* Ap[3]; const float* Bp[3]; int gi[3]; bool ok[3];
#pragma unroll
    for (int t = 0; t < 3; t++) {
        int slot = lane + 32 * t;
        ok[t] = (slot < 83);
        int sl = ok[t] ? slot : 82;
        if (sl < 40)      { Ap[t] = recW + (sl >> 2) * RS;        Bp[t] = xsT + (sl & 3) * RS; }
        else if (sl < 50) { Ap[t] = recW + (sl - 40) * RS;        Bp[t] = xsT + 4 * RS; }
        else if (sl < 80) { int k = sl - 50;
                            Ap[t] = recW + (20 + k / 10) * RS;    Bp[t] = recW + (10 + k % 10) * RS; }
        else              { Ap[t] = recW + (20 + sl - 80) * RS;   Bp[t] = xsT + 4 * RS; }
        gi[t] = (sl < 50) ? sl : sl + 110;
    }
    {
        float a0 = 0.f, a1 = 0.f, a2 = 0.f;
#pragma unroll 5
        for (int s = 0; s < 150; s++) {
            a0 = fmaf(Ap[0][s], Bp[0][s], a0);
            a1 = fmaf(Ap[1][s], Bp[1][s], a1);
            a2 = fmaf(Ap[2][s], Bp[2][s], a2);
        }
        if (ok[0]) { gout[gi[0]] = a0; ssq = fmaf(a0, a0, ssq); }
        if (ok[1]) { gout[gi[1]] = a1; ssq = fmaf(a1, a1, ssq); }
        if (ok[2]) { gout[gi[2]] = a2; ssq = fmaf(a2, a2, ssq); }
    }
    __syncwarp();

    // ---- transpose-reduce the 110 in-register params (chunks of 32) ----
    float* buf = recW;   // reuse per-warp rec region (needs 32*33 floats)
#pragma unroll
    for (int c = 0; c < 4; c++) {
#pragma unroll
        for (int i = 0; i < 32; i++) {
            buf[i * 33 + lane] = accR[c * 32 + i];
        }
        __syncwarp();
        const float* row = buf + lane * 33;
        float t0 = 0.f, t1 = 0.f, t2 = 0.f, t3 = 0.f;
#pragma unroll
        for (int j = 0; j < 32; j += 4) {
            t0 += row[j + 0]; t1 += row[j + 1];
            t2 += row[j + 2]; t3 += row[j + 3];
        }
        float v = (t0 + t1) + (t2 + t3);
        int p = c * 32 + lane;
        if (p < 110) {
            gout[50 + p] = v;                 // gW2 -> 50..149, gB2 -> 150..159
            ssq = fmaf(v, v, ssq);
        }
        __syncwarp();
    }

    // ---- loss + ssq warp reductions ----
    lossacc += __shfl_xor_sync(0xffffffffu, lossacc, 16);
    lossacc += __shfl_xor_sync(0xffffffffu, lossacc, 8);
    lossacc += __shfl_xor_sync(0xffffffffu, lossacc, 4);
    lossacc += __shfl_xor_sync(0xffffffffu, lossacc, 2);
    lossacc += __shfl_xor_sync(0xffffffffu, lossacc, 1);
    const float loss_b = lossacc * invN;

    ssq += __shfl_xor_sync(0xffffffffu, ssq, 16);
    ssq += __shfl_xor_sync(0xffffffffu, ssq, 8);
    ssq += __shfl_xor_sync(0xffffffffu, ssq, 4);
    ssq += __shfl_xor_sync(0xffffffffu, ssq, 2);
    ssq += __shfl_xor_sync(0xffffffffu, ssq, 1);

    if (lane == 0) {
        atomicAdd(&g_sumsq, ssq);
        wout[386] = loss_b;
        wout[387] = clip1e4(fv[b] - loss_b);
    }
}

// Apply global grad-norm clip coefficient to the grad columns [193, 386).
__global__ void k_scale(float* __restrict__ out) {
    const float coef = fminf(1.f, 10.f / (sqrtf(g_sumsq) + 1e-6f));
    const int b = blockIdx.x;
    const int k = threadIdx.x;
    if (k < 193) {
        size_t idx = (size_t)b * 388 + 193 + k;
        out[idx] *= coef;
    }
}

extern "C" void kernel_launch(void* const* d_in, const int* in_sizes, int n_in,
                              void* d_out, int out_size)
{
    const float* W1 = (const float*)d_in[0];
    const float* b1 = (const float*)d_in[1];
    const float* W2 = (const float*)d_in[2];
    const float* b2 = (const float*)d_in[3];
    const float* W3 = (const float*)d_in[4];
    const float* b3 = (const float*)d_in[5];
    const float* G1 = (const float*)d_in[6];
    const float* G2 = (const float*)d_in[7];
    const float* G3 = (const float*)d_in[8];
    const float* G4 = (const float*)d_in[9];
    const float* G5 = (const float*)d_in[10];
    const float* G6 = (const float*)d_in[11];
    const float* dx = (const float*)d_in[12];
    const float* fv = (const float*)d_in[13];
    const int*   dy = (const int*)d_in[14];
    const int*   ss = (const int*)d_in[15];
    float* out = (float*)d_out;

    const int B = in_sizes[13];   // func_val is [B]

    k_zero<<<1, 1>>>();
    k_main<<<B / WPB, BDIM>>>(W1, b1, W2, b2, W3, b3,
                              G1, G2, G3, G4, G5, G6,
                              dx, fv, dy, ss, out);
    k_scale<<<B, 256>>>(out);
}

// round 3
// speedup vs baseline: 1.8483x; 1.1437x over previous
#include <cuda_runtime.h>

#define BDIM 64
#define WPB 2            // warps (MLPs) per block
#define RS 154           // rec row stride in floats (even -> 8B-aligned rows)
#define RECW (23 * RS)   // per-warp rec floats: rows dh1m[10], h2[10], d[3]
#define PSTRIDE 272      // per-MLP param smem floats

typedef unsigned long long u64;

__constant__ float c_lr[6] = {0.001f, 0.01f, 0.05f, 0.1f, 0.5f, 1.0f};
__device__ float g_sumsq = 0.f;   // zeroed by k_zero at END of each call

__device__ __forceinline__ float clip1e4(float v) {
    return fminf(fmaxf(v, -10000.f), 10000.f);
}

__device__ __forceinline__ u64 pk(float lo, float hi) {
    u64 r; asm("mov.b64 %0, {%1,%2};" : "=l"(r) : "f"(lo), "f"(hi)); return r;
}
__device__ __forceinline__ void upk(u64 v, float& lo, float& hi) {
    asm("mov.b64 {%0,%1}, %2;" : "=f"(lo), "=f"(hi) : "l"(v));
}
__device__ __forceinline__ u64 ffma2(u64 a, u64 b, u64 c) {
    u64 d; asm("fma.rn.f32x2 %0, %1, %2, %3;" : "=l"(d) : "l"(a), "l"(b), "l"(c));
    return d;
}
__device__ __forceinline__ u64 fmul2(u64 a, u64 b) {
    u64 d; asm("mul.rn.f32x2 %0, %1, %2;" : "=l"(d) : "l"(a), "l"(b)); return d;
}

__global__ void k_zero() { g_sumsq = 0.f; }

__global__ void __launch_bounds__(BDIM) k_main(
    const float* __restrict__ W1, const float* __restrict__ b1,
    const float* __restrict__ W2, const float* __restrict__ b2,
    const float* __restrict__ W3, const float* __restrict__ b3,
    const float* __restrict__ G1, const float* __restrict__ G2,
    const float* __restrict__ G3, const float* __restrict__ G4,
    const float* __restrict__ G5, const float* __restrict__ G6,
    const float* __restrict__ dx, const float* __restrict__ fv,
    const int* __restrict__ dy, const int* __restrict__ ss,
    float* __restrict__ out)
{
    // xsT rows 0..3 = x features (transposed), row 4 = ones
    __shared__ __align__(16) float xsT[5 * RS];
    __shared__ int   ys[152];
    __shared__ __align__(16) float ps[WPB * PSTRIDE];
    __shared__ __align__(16) float rec[WPB * RECW];

    const int tid  = threadIdx.x;
    const int lane = tid & 31;
    const int warp = tid >> 5;
    const int b    = blockIdx.x * WPB + warp;

    for (int i = tid; i < 150; i += BDIM) {
        const float4 xv = ((const float4*)dx)[i];
        xsT[0 * RS + i] = xv.x;
        xsT[1 * RS + i] = xv.y;
        xsT[2 * RS + i] = xv.z;
        xsT[3 * RS + i] = xv.w;
        xsT[4 * RS + i] = 1.f;
        ys[i] = dy[i];
    }

    float* P    = ps  + warp * PSTRIDE;
    float* recW = rec + warp * RECW;
    // P layout (floats): 0:W1[10x4]  40:b1[10]  52:W2 rows stride 12 (10 rows)
    // 172:b2[10]  184:W3 rows stride 12 (3 rows)  220:b3[3]  224:W3^T stride 4

    const float lr = c_lr[ss[b]];
    float* wout = out + (size_t)b * 388;

    // ---- SGD update into SMEM, clipped params to output ----
    for (int k = lane; k < 40; k += 32) {
        float p = fmaf(-lr, G1[b * 40 + k], W1[b * 40 + k]);
        P[k] = p; wout[k] = clip1e4(p);
    }
    for (int k = lane; k < 10; k += 32) {
        float p = fmaf(-lr, G2[b * 10 + k], b1[b * 10 + k]);
        P[40 + k] = p; wout[40 + k] = clip1e4(p);
    }
    for (int k = lane; k < 100; k += 32) {
        float p = fmaf(-lr, G3[b * 100 + k], W2[b * 100 + k]);
        int r = k / 10, c = k - r * 10;
        P[52 + 12 * r + c] = p; wout[50 + k] = clip1e4(p);
    }
    for (int k = lane; k < 10; k += 32) {
        float p = fmaf(-lr, G4[b * 10 + k], b2[b * 10 + k]);
        P[172 + k] = p; wout[150 + k] = clip1e4(p);
    }
    for (int k = lane; k < 30; k += 32) {
        float p = fmaf(-lr, G5[b * 30 + k], W3[b * 30 + k]);
        int r = k / 10, c = k - r * 10;
        P[184 + 12 * r + c] = p;
        P[224 + 4 * c + r]  = p;                     // W3^T for dh2
        wout[160 + k] = clip1e4(p);
    }
    for (int k = lane; k < 3; k += 32) {
        float p = fmaf(-lr, G6[b * 3 + k], b3[b * 3 + k]);
        P[220 + k] = p; wout[190 + k] = clip1e4(p);
    }
    __syncthreads();

    // ---- in-register accumulators: gW2 as 50 packed f32x2, gB2 scalar ----
    u64 accP[50];
#pragma unroll
    for (int k = 0; k < 50; k++) accP[k] = 0ull;
    float gB2[10];
#pragma unroll
    for (int k = 0; k < 10; k++) gB2[k] = 0.f;
    float lossacc = 0.f;
    const float invN = 1.f / 150.f;

    const u64* W2p = (const u64*)&P[52];        // rows: 6 u64 stride (12 floats)
    const u64* W3p = (const u64*)&P[184];

    for (int s = lane; s < 150; s += 32) {
        const float xv0 = xsT[0 * RS + s], xv1 = xsT[1 * RS + s];
        const float xv2 = xsT[2 * RS + s], xv3 = xsT[3 * RS + s];
        const int y = ys[s];

        // layer 1 (scalar)
        float h1[10];
#pragma unroll
        for (int j = 0; j < 10; j++) {
            float4 w = *(const float4*)&P[4 * j];
            float a = fmaf(w.x, xv0, w.y * xv1);
            float c = fmaf(w.z, xv2, w.w * xv3);
            h1[j] = fmaxf(a + c + P[40 + j], 0.f);
        }
        u64 h1p[5];
#pragma unroll
        for (int k = 0; k < 5; k++) h1p[k] = pk(h1[2 * k], h1[2 * k + 1]);

        // layer 2 (packed)
        float h2[10];
#pragma unroll
        for (int g = 0; g < 10; g++) {
            const u64* r = W2p + 6 * g;
            u64 acc = fmul2(r[0], h1p[0]);
            acc = ffma2(r[1], h1p[1], acc);
            acc = ffma2(r[2], h1p[2], acc);
            acc = ffma2(r[3], h1p[3], acc);
            acc = ffma2(r[4], h1p[4], acc);
            float lo, hi; upk(acc, lo, hi);
            float v = fmaxf(lo + hi + P[172 + g], 0.f);
            h2[g] = v;
            recW[(10 + g) * RS + s] = v;             // h2 row
        }
        u64 h2p[5];
#pragma unroll
        for (int k = 0; k < 5; k++) h2p[k] = pk(h2[2 * k], h2[2 * k + 1]);

        // layer 3 logits (packed)
        float lg[3];
#pragma unroll
        for (int o = 0; o < 3; o++) {
            const u64* r = W3p + 6 * o;
            u64 acc = fmul2(r[0], h2p[0]);
            acc = ffma2(r[1], h2p[1], acc);
            acc = ffma2(r[2], h2p[2], acc);
            acc = ffma2(r[3], h2p[3], acc);
            acc = ffma2(r[4], h2p[4], acc);
            float lo, hi; upk(acc, lo, hi);
            lg[o] = lo + hi + P[220 + o];
        }

        // softmax + CE loss
        float m  = fmaxf(lg[0], fmaxf(lg[1], lg[2]));
        float e0 = __expf(lg[0] - m), e1 = __expf(lg[1] - m), e2 = __expf(lg[2] - m);
        float sum = e0 + e1 + e2;
        float inv = __fdividef(1.f, sum);
        float ly  = (y == 0) ? lg[0] : ((y == 1) ? lg[1] : lg[2]);
        lossacc += (m - ly) + __logf(sum);

        float d0 = (e0 * inv - (y == 0 ? 1.f : 0.f)) * invN;
        float d1 = (e1 * inv - (y == 1 ? 1.f : 0.f)) * invN;
        float d2 = (e2 * inv - (y == 2 ? 1.f : 0.f)) * invN;
        recW[20 * RS + s] = d0;                      // d rows (for gW3/gB3)
        recW[21 * RS + s] = d1;
        recW[22 * RS + s] = d2;

        // backward through layer 2 (packed gW2 + dh1)
        u64 dh1p[5];
#pragma unroll
        for (int k = 0; k < 5; k++) dh1p[k] = 0ull;
#pragma unroll
        for (int g = 0; g < 10; g++) {
            float4 wt = *(const float4*)&P[224 + 4 * g];   // W3^T row g
            float dg = fmaf(wt.x, d0, fmaf(wt.y, d1, wt.z * d2));
            dg = (h2[g] > 0.f) ? dg : 0.f;
            gB2[g] += dg;
            u64 dgd = pk(dg, dg);
            const u64* r = W2p + 6 * g;
            accP[5 * g + 0] = ffma2(dgd, h1p[0], accP[5 * g + 0]);
            accP[5 * g + 1] = ffma2(dgd, h1p[1], accP[5 * g + 1]);
            accP[5 * g + 2] = ffma2(dgd, h1p[2], accP[5 * g + 2]);
            accP[5 * g + 3] = ffma2(dgd, h1p[3], accP[5 * g + 3]);
            accP[5 * g + 4] = ffma2(dgd, h1p[4], accP[5 * g + 4]);
            dh1p[0] = ffma2(dgd, r[0], dh1p[0]);
            dh1p[1] = ffma2(dgd, r[1], dh1p[1]);
            dh1p[2] = ffma2(dgd, r[2], dh1p[2]);
            dh1p[3] = ffma2(dgd, r[3], dh1p[3]);
            dh1p[4] = ffma2(dgd, r[4], dh1p[4]);
        }
        // masked layer-1 deltas -> rec rows (gW1/gB1 offloaded)
#pragma unroll
        for (int k = 0; k < 5; k++) {
            float lo, hi; upk(dh1p[k], lo, hi);
            recW[(2 * k)     * RS + s] = (h1[2 * k]     > 0.f) ? lo : 0.f;
            recW[(2 * k + 1) * RS + s] = (h1[2 * k + 1] > 0.f) ? hi : 0.f;
        }
    }
    __syncwarp();

    float ssq = 0.f;
    float* gout = wout + 193;

    // ---- mini-pass: 83 offloaded params as length-150 dot products ----
    // slots: 0..39 gW1[h][f], 40..49 gB1, 50..79 gW3[o][g], 80..82 gB3
    const float* Ap[3]; const float* Bp[3]; int gi[3]; bool ok[3];
#pragma unroll
    for (int t = 0; t < 3; t++) {
        int slot = lane + 32 * t;
        ok[t] = (slot < 83);
        int sl = ok[t] ? slot : 82;
        if (sl < 40)      { Ap[t] = recW + (sl >> 2) * RS;      Bp[t] = xsT + (sl & 3) * RS; }
        else if (sl < 50) { Ap[t] = recW + (sl - 40) * RS;      Bp[t] = xsT + 4 * RS; }
        else if (sl < 80) { int k = sl - 50;
                            Ap[t] = recW + (20 + k / 10) * RS;  Bp[t] = recW + (10 + k % 10) * RS; }
        else              { Ap[t] = recW + (20 + sl - 80) * RS; Bp[t] = xsT + 4 * RS; }
        gi[t] = (sl < 50) ? sl : sl + 110;
    }
    {
        u64 a0 = 0ull, a1 = 0ull, a2 = 0ull;
        const u64* A0 = (const u64*)Ap[0]; const u64* B0 = (const u64*)Bp[0];
        const u64* A1 = (const u64*)Ap[1]; const u64* B1 = (const u64*)Bp[1];
        const u64* A2 = (const u64*)Ap[2]; const u64* B2 = (const u64*)Bp[2];
#pragma unroll 5
        for (int s = 0; s < 75; s++) {
            a0 = ffma2(A0[s], B0[s], a0);
            a1 = ffma2(A1[s], B1[s], a1);
            a2 = ffma2(A2[s], B2[s], a2);
        }
        float lo, hi, v;
        upk(a0, lo, hi); v = lo + hi;
        if (ok[0]) { gout[gi[0]] = v; ssq = fmaf(v, v, ssq); }
        upk(a1, lo, hi); v = lo + hi;
        if (ok[1]) { gout[gi[1]] = v; ssq = fmaf(v, v, ssq); }
        upk(a2, lo, hi); v = lo + hi;
        if (ok[2]) { gout[gi[2]] = v; ssq = fmaf(v, v, ssq); }
    }
    __syncwarp();

    // ---- transpose-reduce the 110 in-register params (chunks of 32) ----
    float* buf = recW;   // reuse per-warp rec region (needs 32*33 floats)
#pragma unroll
    for (int c = 0; c < 4; c++) {
#pragma unroll
        for (int i = 0; i < 32; i++) {
            int p = c * 32 + i;
            float val;
            if (p < 100) {
                float lo, hi; upk(accP[5 * (p / 10) + (p % 10) / 2], lo, hi);
                val = ((p % 10) & 1) ? hi : lo;
            } else if (p < 110) {
                val = gB2[p - 100];
            } else {
                val = 0.f;
            }
            buf[i * 33 + lane] = val;
        }
        __syncwarp();
        const float* row = buf + lane * 33;
        float t0 = 0.f, t1 = 0.f, t2 = 0.f, t3 = 0.f;
#pragma unroll
        for (int j = 0; j < 32; j += 4) {
            t0 += row[j + 0]; t1 += row[j + 1];
            t2 += row[j + 2]; t3 += row[j + 3];
        }
        float v = (t0 + t1) + (t2 + t3);
        int p = c * 32 + lane;
        if (p < 110) {
            gout[50 + p] = v;                 // gW2 -> 50..149, gB2 -> 150..159
            ssq = fmaf(v, v, ssq);
        }
        __syncwarp();
    }

    // ---- loss + ssq warp reductions ----
    lossacc += __shfl_xor_sync(0xffffffffu, lossacc, 16);
    lossacc += __shfl_xor_sync(0xffffffffu, lossacc, 8);
    lossacc += __shfl_xor_sync(0xffffffffu, lossacc, 4);
    lossacc += __shfl_xor_sync(0xffffffffu, lossacc, 2);
    lossacc += __shfl_xor_sync(0xffffffffu, lossacc, 1);
    const float loss_b = lossacc * invN;

    ssq += __shfl_xor_sync(0xffffffffu, ssq, 16);
    ssq += __shfl_xor_sync(0xffffffffu, ssq, 8);
    ssq += __shfl_xor_sync(0xffffffffu, ssq, 4);
    ssq += __shfl_xor_sync(0xffffffffu, ssq, 2);
    ssq += __shfl_xor_sync(0xffffffffu, ssq, 1);

    if (lane == 0) {
        atomicAdd(&g_sumsq, ssq);
        wout[386] = loss_b;
        wout[387] = clip1e4(fv[b] - loss_b);
    }
}

// Apply global grad-norm clip coefficient to the grad columns [193, 386).
__global__ void k_scale(float* __restrict__ out) {
    const float coef = fminf(1.f, 10.f / (sqrtf(g_sumsq) + 1e-6f));
    const int b = blockIdx.x;
    const int k = threadIdx.x;
    if (k < 193) {
        size_t idx = (size_t)b * 388 + 193 + k;
        out[idx] *= coef;
    }
}

extern "C" void kernel_launch(void* const* d_in, const int* in_sizes, int n_in,
                              void* d_out, int out_size)
{
    const float* W1 = (const float*)d_in[0];
    const float* b1 = (const float*)d_in[1];
    const float* W2 = (const float*)d_in[2];
    const float* b2 = (const float*)d_in[3];
    const float* W3 = (const float*)d_in[4];
    const float* b3 = (const float*)d_in[5];
    const float* G1 = (const float*)d_in[6];
    const float* G2 = (const float*)d_in[7];
    const float* G3 = (const float*)d_in[8];
    const float* G4 = (const float*)d_in[9];
    const float* G5 = (const float*)d_in[10];
    const float* G6 = (const float*)d_in[11];
    const float* dx = (const float*)d_in[12];
    const float* fv = (const float*)d_in[13];
    const int*   dy = (const int*)d_in[14];
    const int*   ss = (const int*)d_in[15];
    float* out = (float*)d_out;

    const int B = in_sizes[13];   // func_val is [B]

    // g_sumsq is 0 on entry: static init on first call, k_zero (below) after.
    k_main<<<B / WPB, BDIM>>>(W1, b1, W2, b2, W3, b3,
                              G1, G2, G3, G4, G5, G6,
                              dx, fv, dy, ss, out);
    k_scale<<<B, 224>>>(out);
    k_zero<<<1, 1>>>();          // reset for the next (graph-replayed) call
}